// round 3
// baseline (speedup 1.0000x reference)
#include <cuda_runtime.h>
#include <cuda_bf16.h>

#define NHID    128
#define K2      256      // 2*NHID
#define TILE_E  64       // edges per tile
#define A_STRIDE 260     // padded row stride (floats) for the edge-feature tile
#define THREADS 256

// Dynamic smem layout (floats):
//   W1s : K2*NHID            = 32768
//   As  : TILE_E*A_STRIDE    = 16640
//   W2s : NHID               = 128
//   b1s : NHID               = 128
//   idxs: 2*TILE_E ints      = 128 (as 4B each)
#define SMEM_FLOATS (K2*NHID + TILE_E*A_STRIDE + NHID + NHID + 2*TILE_E)

// Detect index element stride: int32 data -> 1, int64 data -> 2.
// For int64 (little-endian) with values in [0, 100000), every odd 32-bit
// word is exactly 0. For int32 random indices, odd words are ~never all 0.
__device__ __forceinline__ int detect_idx_stride(const int* p, int n_words)
{
    int stride = 2;
    #pragma unroll 1
    for (int i = 1; i < n_words; i += 2) {
        if (p[i] != 0) { stride = 1; break; }
    }
    return stride;
}

__global__ void __launch_bounds__(THREADS, 1)
mlp_decoder_kernel(const float* __restrict__ inputs,
                   const int* __restrict__ x_idx,
                   const int* __restrict__ y_idx,
                   const float* __restrict__ W1,
                   const float* __restrict__ bias1,
                   const float* __restrict__ W2,
                   const float* __restrict__ bias2,
                   float* __restrict__ out,
                   int n_edges, int n_tiles)
{
    extern __shared__ float smem[];
    float* W1s  = smem;                          // 32768 floats (128 KB)
    float* As   = W1s + K2 * NHID;               // 16640 floats
    float* W2s  = As + TILE_E * A_STRIDE;        // 128
    float* b1s  = W2s + NHID;                    // 128
    int*   idxs = (int*)(b1s + NHID);            // 128 ints: [0:64) x, [64:128) y

    const int tid = threadIdx.x;
    const int tx  = tid & 15;    // output group 0..15
    const int ty  = tid >> 4;    // edge group 0..15 (4 edges each)

    const int probe_n = (n_edges >= 64) ? 128 : (2 * n_edges);
    const int istride = detect_idx_stride(x_idx, probe_n);

    // ---- load weights into smem (once per block) ----
    {
        const float4* src = (const float4*)W1;
        float4* dst = (float4*)W1s;
        for (int i = tid; i < (K2 * NHID) / 4; i += THREADS) dst[i] = src[i];
    }
    if (tid < NHID) { W2s[tid] = W2[tid]; b1s[tid] = bias1[tid]; }
    const float b2 = bias2[0];
    __syncthreads();

    // per-thread constant epilogue params (out columns j = tx + 16*i)
    float b1r[8], w2r[8];
    #pragma unroll
    for (int i = 0; i < 8; i++) {
        b1r[i] = b1s[tx + 16 * i];
        w2r[i] = W2s[tx + 16 * i];
    }

    for (int tile = blockIdx.x; tile < n_tiles; tile += (int)gridDim.x) {
        const int e0 = tile * TILE_E;

        __syncthreads();   // As / idxs are free to overwrite

        // ---- load this tile's indices ----
        if (tid < TILE_E) {
            int e = e0 + tid;
            idxs[tid] = (e < n_edges) ? x_idx[(size_t)e * istride] : 0;
        } else if (tid < 2 * TILE_E) {
            int e = e0 + (tid - TILE_E);
            idxs[tid] = (e < n_edges) ? y_idx[(size_t)e * istride] : 0;
        }
        __syncthreads();

        // ---- gather 64 edges x 256 floats (x -> cols [0,128), y -> [128,256)) ----
        // 64 float4 per edge = 4096 slots; 16 per thread
        #pragma unroll
        for (int it = 0; it < 16; it++) {
            int slot = it * THREADS + tid;
            int e = slot >> 6;       // edge 0..63
            int c = slot & 63;       // float4 slot within the 256-float concat row
            int node, src4;
            if (c < 32) { node = idxs[e];          src4 = c;      }   // x row, float4 0..31
            else        { node = idxs[TILE_E + e]; src4 = c - 32; }   // y row, float4 0..31
            float4 v = ((const float4*)(inputs + (size_t)node * NHID))[src4];
            *(float4*)(As + e * A_STRIDE + c * 4) = v;
        }
        __syncthreads();

        // ---- GEMM: acc[4 edges][8 outs], K = 256 ----
        float acc[4][8];
        #pragma unroll
        for (int e = 0; e < 4; e++)
            #pragma unroll
            for (int i = 0; i < 8; i++) acc[e][i] = 0.f;

        const float* a0p = As + (ty * 4 + 0) * A_STRIDE;
        const float* a1p = As + (ty * 4 + 1) * A_STRIDE;
        const float* a2p = As + (ty * 4 + 2) * A_STRIDE;
        const float* a3p = As + (ty * 4 + 3) * A_STRIDE;

        #pragma unroll 4
        for (int k = 0; k < K2; k++) {
            float a0 = a0p[k], a1 = a1p[k], a2 = a2p[k], a3 = a3p[k];
            float b[8];
            #pragma unroll
            for (int i = 0; i < 8; i++) b[i] = W1s[k * NHID + tx + 16 * i];
            #pragma unroll
            for (int i = 0; i < 8; i++) {
                acc[0][i] = fmaf(a0, b[i], acc[0][i]);
                acc[1][i] = fmaf(a1, b[i], acc[1][i]);
                acc[2][i] = fmaf(a2, b[i], acc[2][i]);
                acc[3][i] = fmaf(a3, b[i], acc[3][i]);
            }
        }

        // ---- fused epilogue: bias1 + relu + dot(W2) + reduce + sigmoid ----
        #pragma unroll
        for (int e = 0; e < 4; e++) {
            float s = 0.f;
            #pragma unroll
            for (int i = 0; i < 8; i++) {
                float h = acc[e][i] + b1r[i];
                h = fmaxf(h, 0.f);
                s = fmaf(h, w2r[i], s);
            }
            // reduce across the 16 tx lanes
            s += __shfl_xor_sync(0xffffffffu, s, 1, 16);
            s += __shfl_xor_sync(0xffffffffu, s, 2, 16);
            s += __shfl_xor_sync(0xffffffffu, s, 4, 16);
            s += __shfl_xor_sync(0xffffffffu, s, 8, 16);
            if (tx == 0) {
                int eg = e0 + ty * 4 + e;
                if (eg < n_edges)
                    out[eg] = 1.f / (1.f + __expf(-(s + b2)));
            }
        }
    }
}

extern "C" void kernel_launch(void* const* d_in, const int* in_sizes, int n_in,
                              void* d_out, int out_size) {
    const float* inputs = (const float*)d_in[0];
    const int*   xi     = (const int*)d_in[1];
    const int*   yi     = (const int*)d_in[2];
    const float* W1     = (const float*)d_in[3];
    const float* b1     = (const float*)d_in[4];
    const float* W2     = (const float*)d_in[5];
    const float* b2     = (const float*)d_in[6];
    float* out = (float*)d_out;

    const int n_edges = in_sizes[1];
    const int n_tiles = (n_edges + TILE_E - 1) / TILE_E;

    const size_t smem_bytes = SMEM_FLOATS * sizeof(float);
    cudaFuncSetAttribute(mlp_decoder_kernel,
                         cudaFuncAttributeMaxDynamicSharedMemorySize,
                         (int)smem_bytes);

    int dev = 0, nsm = 148;
    cudaGetDevice(&dev);
    cudaDeviceGetAttribute(&nsm, cudaDevAttrMultiProcessorCount, dev);
    int grid = nsm < n_tiles ? nsm : n_tiles;

    mlp_decoder_kernel<<<grid, THREADS, smem_bytes>>>(
        inputs, xi, yi, W1, b1, W2, b2, out, n_edges, n_tiles);
}

// round 5
// speedup vs baseline: 2.7312x; 2.7312x over previous
#include <cuda_runtime.h>
#include <cuda_bf16.h>
#include <cstdint>

#define NHID    128
#define K2      256
#define TILE_E  64
#define THREADS 256

// bf16 row stride (elements) for padded SMEM tiles: 264*2 = 528 bytes (odd # of 16B -> conflict-free ldmatrix)
#define RSTR    264
#define RSTRB   528

// ---- SMEM layout (bytes) ----
#define SM_BHI   0                         // W1^T hi: 128 x 264 bf16 = 67584
#define SM_BLO   67584
#define SM_AHI   135168                    // A hi: 64 x 264 bf16 = 33792
#define SM_ALO   168960
#define SM_B1    202752                    // bias1: 128 f32
#define SM_W2    203264                    // W2: 128 f32
#define SM_PART  203776                    // 64 f32 row partials
#define SM_IDX   204032                    // 128 int
#define SM_TOTAL 204800

__device__ __forceinline__ uint32_t smem_u32(const void* p) {
    uint32_t a;
    asm("{ .reg .u64 t; cvta.to.shared.u64 t, %1; cvt.u32.u64 %0, t; }" : "=r"(a) : "l"(p));
    return a;
}

__device__ __forceinline__ void ldsm_x4(uint32_t addr, uint32_t r[4]) {
    asm volatile("ldmatrix.sync.aligned.m8n8.x4.shared.b16 {%0,%1,%2,%3}, [%4];"
                 : "=r"(r[0]), "=r"(r[1]), "=r"(r[2]), "=r"(r[3]) : "r"(addr));
}

__device__ __forceinline__ void mma_bf16(float c[4], const uint32_t a[4], uint32_t b0, uint32_t b1) {
    asm volatile("mma.sync.aligned.m16n8k16.row.col.f32.bf16.bf16.f32 "
                 "{%0,%1,%2,%3}, {%4,%5,%6,%7}, {%8,%9}, {%0,%1,%2,%3};"
                 : "+f"(c[0]), "+f"(c[1]), "+f"(c[2]), "+f"(c[3])
                 : "r"(a[0]), "r"(a[1]), "r"(a[2]), "r"(a[3]), "r"(b0), "r"(b1));
}

// int32 data -> stride 1; int64 (LE, values < 1e5) -> every odd word 0 -> stride 2
__device__ __forceinline__ int detect_idx_stride(const int* p, int n_words) {
    int stride = 2;
    #pragma unroll 1
    for (int i = 1; i < n_words; i += 2)
        if (p[i] != 0) { stride = 1; break; }
    return stride;
}

__global__ void __launch_bounds__(THREADS, 1)
mlp_decoder_hmma_kernel(const float* __restrict__ inputs,
                        const int* __restrict__ x_idx,
                        const int* __restrict__ y_idx,
                        const float* __restrict__ W1,
                        const float* __restrict__ bias1,
                        const float* __restrict__ W2,
                        const float* __restrict__ bias2,
                        float* __restrict__ out,
                        int n_edges, int n_tiles)
{
    extern __shared__ char smem[];
    const uint32_t sb  = smem_u32(smem);
    const int tid  = threadIdx.x;
    const int lane = tid & 31;
    const int wid  = tid >> 5;
    const int mw   = wid & 3;     // m-tile: rows [mw*16, mw*16+16)
    const int nw   = wid >> 2;    // n half: cols [nw*64, nw*64+64)

    const int probe_n = (n_edges >= 64) ? 128 : (2 * n_edges);
    const int istride = detect_idx_stride(x_idx, probe_n);

    // ---- one-time: W1 -> bf16 hi/lo as B^T [n][k] padded rows ----
    {
        __nv_bfloat16* bhi = (__nv_bfloat16*)(smem + SM_BHI);
        __nv_bfloat16* blo = (__nv_bfloat16*)(smem + SM_BLO);
        for (int i = tid; i < NHID * K2; i += THREADS) {
            int n = i & (NHID - 1);
            int k = i >> 7;
            float v = W1[k * NHID + n];          // B^T[n][k] = W1[k][n]
            __nv_bfloat16 h = __float2bfloat16_rn(v);
            __nv_bfloat16 l = __float2bfloat16_rn(v - __bfloat162float(h));
            bhi[n * RSTR + k] = h;
            blo[n * RSTR + k] = l;
        }
        if (tid < NHID) {
            ((float*)(smem + SM_B1))[tid] = bias1[tid];
            ((float*)(smem + SM_W2))[tid] = W2[tid];
        }
    }
    const float b2 = bias2[0];
    __syncthreads();

    // per-thread epilogue constants: cols n = nw*64 + nt*8 + (lane&3)*2 + {0,1}
    float b1v[16], w2v[16];
    {
        const float* b1s = (const float*)(smem + SM_B1);
        const float* w2s = (const float*)(smem + SM_W2);
        #pragma unroll
        for (int nt = 0; nt < 8; nt++) {
            int n = nw * 64 + nt * 8 + (lane & 3) * 2;
            b1v[2 * nt]     = b1s[n];
            b1v[2 * nt + 1] = b1s[n + 1];
            w2v[2 * nt]     = w2s[n];
            w2v[2 * nt + 1] = w2s[n + 1];
        }
    }

    // ldmatrix per-lane address components
    const uint32_t a_lane = (uint32_t)(lane & 15) * RSTRB + (uint32_t)(lane >> 4) * 16;
    const uint32_t b_lane = (uint32_t)((lane & 7) + ((lane >> 4) << 3)) * RSTRB
                          + (uint32_t)((lane >> 3) & 1) * 16;

    const uint32_t aHi = sb + SM_AHI + (uint32_t)mw * 16 * RSTRB + a_lane;
    const uint32_t aLo = aHi + (SM_ALO - SM_AHI);
    const uint32_t bHi = sb + SM_BHI + (uint32_t)nw * 64 * RSTRB + b_lane;
    const uint32_t bLo = bHi + (SM_BLO - SM_BHI);

    int*   idxs = (int*)(smem + SM_IDX);
    float* part = (float*)(smem + SM_PART);

    for (int tile = blockIdx.x; tile < n_tiles; tile += (int)gridDim.x) {
        const int e0 = tile * TILE_E;

        __syncthreads();   // previous tile fully consumed (A, idxs, part free)

        if (tid < 2 * TILE_E) {
            int r = tid & 63;
            int e = e0 + r;
            int es = (e < n_edges) ? e : 0;
            idxs[tid] = (tid < TILE_E) ? x_idx[(size_t)es * istride]
                                       : y_idx[(size_t)es * istride];
        }
        __syncthreads();

        // ---- gather + bf16 split: 64 rows x 64 float4 slots ----
        #pragma unroll
        for (int it = 0; it < 16; it++) {
            int slot = it * THREADS + tid;
            int row  = slot >> 6;          // 0..63
            int c4   = slot & 63;          // float4 index in concat row
            int node = (c4 < 32) ? idxs[row] : idxs[64 + row];
            int src4 = c4 & 31;
            float4 v = __ldg((const float4*)(inputs + (size_t)node * NHID) + src4);

            __nv_bfloat162 h0 = __float22bfloat162_rn(make_float2(v.x, v.y));
            __nv_bfloat162 h1 = __float22bfloat162_rn(make_float2(v.z, v.w));
            float2 r0 = __bfloat1622float2(h0);
            float2 r1 = __bfloat1622float2(h1);
            __nv_bfloat162 l0 = __float22bfloat162_rn(make_float2(v.x - r0.x, v.y - r0.y));
            __nv_bfloat162 l1 = __float22bfloat162_rn(make_float2(v.z - r1.x, v.w - r1.y));

            uint32_t off = (uint32_t)row * RSTRB + (uint32_t)c4 * 8;
            *(uint2*)(smem + SM_AHI + off) =
                make_uint2(*(uint32_t*)&h0, *(uint32_t*)&h1);
            *(uint2*)(smem + SM_ALO + off) =
                make_uint2(*(uint32_t*)&l0, *(uint32_t*)&l1);
        }
        __syncthreads();

        // ---- MMA mainloop: 16 K-chunks x 8 n-tiles x 3 split products ----
        float c[8][4];
        #pragma unroll
        for (int nt = 0; nt < 8; nt++)
            #pragma unroll
            for (int j = 0; j < 4; j++) c[nt][j] = 0.f;

        #pragma unroll 2
        for (int kc = 0; kc < 16; kc++) {
            uint32_t ah[4], al[4];
            ldsm_x4(aHi + kc * 32, ah);
            ldsm_x4(aLo + kc * 32, al);
            #pragma unroll
            for (int pr = 0; pr < 4; pr++) {
                uint32_t bh[4], bl[4];
                ldsm_x4(bHi + (uint32_t)pr * 16 * RSTRB + kc * 32, bh);
                ldsm_x4(bLo + (uint32_t)pr * 16 * RSTRB + kc * 32, bl);
                mma_bf16(c[2 * pr],     ah, bh[0], bh[1]);
                mma_bf16(c[2 * pr + 1], ah, bh[2], bh[3]);
                mma_bf16(c[2 * pr],     ah, bl[0], bl[1]);
                mma_bf16(c[2 * pr + 1], ah, bl[2], bl[3]);
                mma_bf16(c[2 * pr],     al, bh[0], bh[1]);
                mma_bf16(c[2 * pr + 1], al, bh[2], bh[3]);
            }
        }

        // ---- epilogue: bias + relu + W2 dot (per-thread cols), reduce ----
        float p0 = 0.f, p1 = 0.f;   // rows mw*16 + g and +8  (g = lane>>2)
        #pragma unroll
        for (int nt = 0; nt < 8; nt++) {
            p0 = fmaf(fmaxf(c[nt][0] + b1v[2*nt],     0.f), w2v[2*nt],     p0);
            p0 = fmaf(fmaxf(c[nt][1] + b1v[2*nt + 1], 0.f), w2v[2*nt + 1], p0);
            p1 = fmaf(fmaxf(c[nt][2] + b1v[2*nt],     0.f), w2v[2*nt],     p1);
            p1 = fmaf(fmaxf(c[nt][3] + b1v[2*nt + 1], 0.f), w2v[2*nt + 1], p1);
        }
        // reduce over the 4 lanes of the group (cols)
        p0 += __shfl_xor_sync(0xffffffffu, p0, 1, 32);
        p0 += __shfl_xor_sync(0xffffffffu, p0, 2, 32);
        p1 += __shfl_xor_sync(0xffffffffu, p1, 1, 32);
        p1 += __shfl_xor_sync(0xffffffffu, p1, 2, 32);

        const int g  = lane >> 2;
        const int r0 = mw * 16 + g;
        if (nw == 1 && (lane & 3) == 0) {
            part[r0]     = p0;
            part[r0 + 8] = p1;
        }
        __syncthreads();
        if (nw == 0 && (lane & 3) == 0) {
            int ea = e0 + r0, eb = e0 + r0 + 8;
            if (ea < n_edges) {
                float t = p0 + part[r0] + b2;
                out[ea] = 1.f / (1.f + __expf(-t));
            }
            if (eb < n_edges) {
                float t = p1 + part[r0 + 8] + b2;
                out[eb] = 1.f / (1.f + __expf(-t));
            }
        }
    }
}

extern "C" void kernel_launch(void* const* d_in, const int* in_sizes, int n_in,
                              void* d_out, int out_size) {
    const float* inputs = (const float*)d_in[0];
    const int*   xi     = (const int*)d_in[1];
    const int*   yi     = (const int*)d_in[2];
    const float* W1     = (const float*)d_in[3];
    const float* b1     = (const float*)d_in[4];
    const float* W2     = (const float*)d_in[5];
    const float* b2     = (const float*)d_in[6];
    float* out = (float*)d_out;

    const int n_edges = in_sizes[1];
    const int n_tiles = (n_edges + TILE_E - 1) / TILE_E;

    cudaFuncSetAttribute(mlp_decoder_hmma_kernel,
                         cudaFuncAttributeMaxDynamicSharedMemorySize, SM_TOTAL);

    int dev = 0, nsm = 148;
    cudaGetDevice(&dev);
    cudaDeviceGetAttribute(&nsm, cudaDevAttrMultiProcessorCount, dev);
    int grid = nsm < n_tiles ? nsm : n_tiles;

    mlp_decoder_hmma_kernel<<<grid, THREADS, SM_TOTAL>>>(
        inputs, xi, yi, W1, b1, W2, b2, out, n_edges, n_tiles);
}

// round 6
// speedup vs baseline: 5.7740x; 2.1141x over previous
#include <cuda_runtime.h>
#include <cuda_fp16.h>
#include <cstdint>

#define NHID    128
#define K2      256
#define TILE_E  64
#define THREADS 256

// A tile: fp16, padded rows of 264 halves = 528 B (odd 16B count -> conflict-free ldmatrix)
#define ARSTR   528

// ---- SMEM layout (bytes) ----
#define SM_B     0         // W1^T fp16, 128 rows x 512 B, XOR-swizzled chunks  (65536)
#define SM_A     65536     // A fp16, 64 x 528 B                                 (33792)
#define SM_ST0   99328     // stage 0: fp32 gather, 64 x 1024 B                  (65536)
#define SM_ST1   164864    // stage 1                                            (65536)
#define SM_B1    230400    // bias1 f32[128]
#define SM_W2    230912    // W2 f32[128]
#define SM_PART  231424    // f32[64]
#define SM_TOTAL 231680

__device__ __forceinline__ uint32_t smem_u32(const void* p) {
    uint32_t a;
    asm("{ .reg .u64 t; cvta.to.shared.u64 t, %1; cvt.u32.u64 %0, t; }" : "=r"(a) : "l"(p));
    return a;
}
__device__ __forceinline__ void ldsm_x4(uint32_t addr, uint32_t r[4]) {
    asm volatile("ldmatrix.sync.aligned.m8n8.x4.shared.b16 {%0,%1,%2,%3}, [%4];"
                 : "=r"(r[0]), "=r"(r[1]), "=r"(r[2]), "=r"(r[3]) : "r"(addr));
}
__device__ __forceinline__ void mma_fp16(float c[4], const uint32_t a[4], uint32_t b0, uint32_t b1) {
    asm volatile("mma.sync.aligned.m16n8k16.row.col.f32.f16.f16.f32 "
                 "{%0,%1,%2,%3}, {%4,%5,%6,%7}, {%8,%9}, {%0,%1,%2,%3};"
                 : "+f"(c[0]), "+f"(c[1]), "+f"(c[2]), "+f"(c[3])
                 : "r"(a[0]), "r"(a[1]), "r"(a[2]), "r"(a[3]), "r"(b0), "r"(b1));
}
__device__ __forceinline__ void cp_async16(uint32_t dst, const void* src) {
    asm volatile("cp.async.cg.shared.global [%0], [%1], 16;" :: "r"(dst), "l"(src) : "memory");
}
#define CP_COMMIT() asm volatile("cp.async.commit_group;" ::: "memory")
#define CP_WAIT0()  asm volatile("cp.async.wait_group 0;" ::: "memory")

// int32 data -> stride 1; int64 (LE, values < 1e5) -> every odd word 0 -> stride 2
__device__ __forceinline__ int detect_idx_stride(const int* p, int n_words) {
    int stride = 2;
    #pragma unroll 1
    for (int i = 1; i < n_words; i += 2)
        if (p[i] != 0) { stride = 1; break; }
    return stride;
}

__global__ void __launch_bounds__(THREADS, 1)
mlp_decoder_hmma2_kernel(const float* __restrict__ inputs,
                         const int* __restrict__ x_idx,
                         const int* __restrict__ y_idx,
                         const float* __restrict__ W1,
                         const float* __restrict__ bias1,
                         const float* __restrict__ W2,
                         const float* __restrict__ bias2,
                         float* __restrict__ out,
                         int n_edges, int n_tiles)
{
    extern __shared__ char smem[];
    const uint32_t sb  = smem_u32(smem);
    const int tid  = threadIdx.x;
    const int lane = tid & 31;
    const int wid  = tid >> 5;
    const int mw   = wid & 3;     // m-tile: rows [mw*16, +16)
    const int nw   = wid >> 2;    // n half: cols [nw*64, +64)

    const int probe_n = (n_edges >= 64) ? 128 : (2 * n_edges);
    const int istride = detect_idx_stride(x_idx, probe_n);

    // ---- one-time: W1 -> fp16 B^T[n][k], XOR-swizzled 16B chunks ----
    for (int i = tid; i < NHID * K2; i += THREADS) {
        int n = i & (NHID - 1);
        int k = i >> 7;
        __half h = __float2half_rn(W1[k * NHID + n]);
        uint32_t off = (uint32_t)n * 512u + (uint32_t)(((k >> 3) ^ (n & 7)) << 4)
                     + (uint32_t)(k & 7) * 2u;
        *(__half*)(smem + SM_B + off) = h;
    }
    if (tid < NHID) {
        ((float*)(smem + SM_B1))[tid] = bias1[tid];
        ((float*)(smem + SM_W2))[tid] = W2[tid];
    }
    const float b2 = bias2[0];
    __syncthreads();

    // epilogue constants: cols n = nw*64 + nt*8 + (lane&3)*2 + {0,1}
    float b1v[16], w2v[16];
    {
        const float* b1s = (const float*)(smem + SM_B1);
        const float* w2s = (const float*)(smem + SM_W2);
        #pragma unroll
        for (int nt = 0; nt < 8; nt++) {
            int n = nw * 64 + nt * 8 + (lane & 3) * 2;
            b1v[2*nt] = b1s[n];   b1v[2*nt+1] = b1s[n+1];
            w2v[2*nt] = w2s[n];   w2v[2*nt+1] = w2s[n+1];
        }
    }

    // ldmatrix lane addressing
    const uint32_t aAddr = sb + SM_A + (uint32_t)mw * 16 * ARSTR
                         + (uint32_t)(lane & 15) * ARSTR + (uint32_t)(lane >> 4) * 16;
    const uint32_t sw   = (uint32_t)(lane & 7);
    const uint32_t kbit = (uint32_t)((lane >> 3) & 1);
    uint32_t bBase[4];
    {
        uint32_t row_l = (uint32_t)((lane & 7) + ((lane >> 4) << 3));  // 0..15
        #pragma unroll
        for (int pr = 0; pr < 4; pr++)
            bBase[pr] = sb + SM_B + ((uint32_t)nw * 64 + (uint32_t)pr * 16 + row_l) * 512u;
    }

    float* part = (float*)(smem + SM_PART);

    // per-thread gather slot geometry (same for every tile)
    // slot = it*256 + tid: row = slot>>6, c4 = slot&63
    const int c4   = tid & 63;
    const int row0 = tid >> 6;          // rows rowo, rowo+4, ... (16 rows)
    const bool is_x = (c4 < 32);
    const int  src4 = c4 & 31;

    // ---- prologue: prefetch tile blockIdx.x into stage 0 ----
    {
        int tile = blockIdx.x;
        if (tile < n_tiles) {
            int e0 = tile * TILE_E;
            #pragma unroll 4
            for (int it = 0; it < 16; it++) {
                int row = row0 + it * 4;
                int e = e0 + row;
                int es = (e < n_edges) ? e : 0;
                int node = is_x ? x_idx[(size_t)es * istride] : y_idx[(size_t)es * istride];
                cp_async16(sb + SM_ST0 + (uint32_t)row * 1024u + (uint32_t)c4 * 16u,
                           inputs + (size_t)node * NHID + src4 * 4);
            }
        }
        CP_COMMIT();
    }

    uint32_t buf = 0;
    for (int tile = blockIdx.x; tile < n_tiles; tile += (int)gridDim.x) {
        const int e0 = tile * TILE_E;
        const uint32_t stage = buf ? (uint32_t)SM_ST1 : (uint32_t)SM_ST0;

        CP_WAIT0();
        __syncthreads();   // stage[buf] visible to all; previous tile fully done (A free)

        // ---- convert stage fp32 -> A fp16 ----
        #pragma unroll 4
        for (int it = 0; it < 16; it++) {
            int row = row0 + it * 4;
            float4 v = *(const float4*)(smem + stage + (uint32_t)row * 1024u + (uint32_t)c4 * 16u);
            __half2 h0 = __float22half2_rn(make_float2(v.x, v.y));
            __half2 h1 = __float22half2_rn(make_float2(v.z, v.w));
            *(uint2*)(smem + SM_A + (uint32_t)row * ARSTR + (uint32_t)c4 * 8u) =
                make_uint2(*(uint32_t*)&h0, *(uint32_t*)&h1);
        }
        __syncthreads();   // A ready

        // ---- prefetch next tile into the other stage (overlaps MMA below) ----
        {
            int ntile = tile + (int)gridDim.x;
            if (ntile < n_tiles) {
                int ne0 = ntile * TILE_E;
                uint32_t nstage = buf ? (uint32_t)SM_ST0 : (uint32_t)SM_ST1;
                #pragma unroll 4
                for (int it = 0; it < 16; it++) {
                    int row = row0 + it * 4;
                    int e = ne0 + row;
                    int es = (e < n_edges) ? e : 0;
                    int node = is_x ? x_idx[(size_t)es * istride] : y_idx[(size_t)es * istride];
                    cp_async16(sb + nstage + (uint32_t)row * 1024u + (uint32_t)c4 * 16u,
                               inputs + (size_t)node * NHID + src4 * 4);
                }
            }
            CP_COMMIT();
        }

        // ---- MMA mainloop: 16 K-chunks x 4 pr x 2 ----
        float c[8][4];
        #pragma unroll
        for (int nt = 0; nt < 8; nt++)
            #pragma unroll
            for (int j = 0; j < 4; j++) c[nt][j] = 0.f;

        #pragma unroll
        for (int kc = 0; kc < 16; kc++) {
            uint32_t a[4];
            ldsm_x4(aAddr + (uint32_t)kc * 32u, a);
            uint32_t csw = ((uint32_t)(2 * kc) + kbit) ^ sw;
            #pragma unroll
            for (int pr = 0; pr < 4; pr++) {
                uint32_t b[4];
                ldsm_x4(bBase[pr] + (csw << 4), b);
                mma_fp16(c[2*pr],     a, b[0], b[1]);
                mma_fp16(c[2*pr + 1], a, b[2], b[3]);
            }
        }

        // ---- epilogue: bias + relu + W2 dot, reduce, sigmoid ----
        float p0 = 0.f, p1 = 0.f;
        #pragma unroll
        for (int nt = 0; nt < 8; nt++) {
            p0 = fmaf(fmaxf(c[nt][0] + b1v[2*nt],   0.f), w2v[2*nt],   p0);
            p0 = fmaf(fmaxf(c[nt][1] + b1v[2*nt+1], 0.f), w2v[2*nt+1], p0);
            p1 = fmaf(fmaxf(c[nt][2] + b1v[2*nt],   0.f), w2v[2*nt],   p1);
            p1 = fmaf(fmaxf(c[nt][3] + b1v[2*nt+1], 0.f), w2v[2*nt+1], p1);
        }
        p0 += __shfl_xor_sync(0xffffffffu, p0, 1, 32);
        p0 += __shfl_xor_sync(0xffffffffu, p0, 2, 32);
        p1 += __shfl_xor_sync(0xffffffffu, p1, 1, 32);
        p1 += __shfl_xor_sync(0xffffffffu, p1, 2, 32);

        const int g  = lane >> 2;
        const int r0 = mw * 16 + g;
        if (nw == 1 && (lane & 3) == 0) {
            part[r0]     = p0;
            part[r0 + 8] = p1;
        }
        __syncthreads();
        if (nw == 0 && (lane & 3) == 0) {
            int ea = e0 + r0, eb = e0 + r0 + 8;
            if (ea < n_edges)
                out[ea] = 1.f / (1.f + __expf(-(p0 + part[r0] + b2)));
            if (eb < n_edges)
                out[eb] = 1.f / (1.f + __expf(-(p1 + part[r0 + 8] + b2)));
        }
        buf ^= 1;
    }
}

extern "C" void kernel_launch(void* const* d_in, const int* in_sizes, int n_in,
                              void* d_out, int out_size) {
    const float* inputs = (const float*)d_in[0];
    const int*   xi     = (const int*)d_in[1];
    const int*   yi     = (const int*)d_in[2];
    const float* W1     = (const float*)d_in[3];
    const float* b1     = (const float*)d_in[4];
    const float* W2     = (const float*)d_in[5];
    const float* b2     = (const float*)d_in[6];
    float* out = (float*)d_out;

    const int n_edges = in_sizes[1];
    const int n_tiles = (n_edges + TILE_E - 1) / TILE_E;

    cudaFuncSetAttribute(mlp_decoder_hmma2_kernel,
                         cudaFuncAttributeMaxDynamicSharedMemorySize, SM_TOTAL);

    int dev = 0, nsm = 148;
    cudaGetDevice(&dev);
    cudaDeviceGetAttribute(&nsm, cudaDevAttrMultiProcessorCount, dev);
    int grid = nsm < n_tiles ? nsm : n_tiles;

    mlp_decoder_hmma2_kernel<<<grid, THREADS, SM_TOTAL>>>(
        inputs, xi, yi, W1, b1, W2, b2, out, n_edges, n_tiles);
}

// round 7
// speedup vs baseline: 7.7349x; 1.3396x over previous
#include <cuda_runtime.h>
#include <cuda_fp16.h>
#include <cstdint>

#define NHID    128
#define K2      256
#define TILE_E  32
#define THREADS 256

// A tile: fp16, padded rows of 264 halves = 528 B (odd 16B count -> conflict-free ldmatrix)
#define ARSTR   528

// ---- SMEM layout (bytes) ----
#define SM_B     0         // W1^T fp16, 128 rows x 512 B, XOR-swizzled chunks (65536)
#define SM_A     65536     // A fp16, 32 x 528 B (16896)
#define SM_B1    82432     // bias1 f32[128]
#define SM_W2    82944     // W2 f32[128]
#define SM_PART  83456     // f32[4][32]
#define SM_TOTAL 83968

__device__ __forceinline__ uint32_t smem_u32(const void* p) {
    uint32_t a;
    asm("{ .reg .u64 t; cvta.to.shared.u64 t, %1; cvt.u32.u64 %0, t; }" : "=r"(a) : "l"(p));
    return a;
}
__device__ __forceinline__ void ldsm_x4(uint32_t addr, uint32_t r[4]) {
    asm volatile("ldmatrix.sync.aligned.m8n8.x4.shared.b16 {%0,%1,%2,%3}, [%4];"
                 : "=r"(r[0]), "=r"(r[1]), "=r"(r[2]), "=r"(r[3]) : "r"(addr));
}
__device__ __forceinline__ void mma_fp16(float c[4], const uint32_t a[4], uint32_t b0, uint32_t b1) {
    asm volatile("mma.sync.aligned.m16n8k16.row.col.f32.f16.f16.f32 "
                 "{%0,%1,%2,%3}, {%4,%5,%6,%7}, {%8,%9}, {%0,%1,%2,%3};"
                 : "+f"(c[0]), "+f"(c[1]), "+f"(c[2]), "+f"(c[3])
                 : "r"(a[0]), "r"(a[1]), "r"(a[2]), "r"(a[3]), "r"(b0), "r"(b1));
}

// int32 data -> stride 1; int64 (LE, values < 1e5) -> every odd word 0 -> stride 2
__device__ __forceinline__ int detect_idx_stride(const int* p, int n_words) {
    int stride = 2;
    #pragma unroll 1
    for (int i = 1; i < n_words; i += 2)
        if (p[i] != 0) { stride = 1; break; }
    return stride;
}

__global__ void __launch_bounds__(THREADS, 2)
mlp_decoder_hmma3_kernel(const float* __restrict__ inputs,
                         const int* __restrict__ x_idx,
                         const int* __restrict__ y_idx,
                         const float* __restrict__ W1,
                         const float* __restrict__ bias1,
                         const float* __restrict__ W2,
                         const float* __restrict__ bias2,
                         float* __restrict__ out,
                         int n_edges, int n_tiles)
{
    extern __shared__ char smem[];
    const uint32_t sb  = smem_u32(smem);
    const int tid  = threadIdx.x;
    const int lane = tid & 31;
    const int wid  = tid >> 5;
    const int mw   = wid & 1;     // m-tile: rows [mw*16, +16)
    const int nw   = wid >> 1;    // n quarter: cols [nw*32, +32)

    const int probe_n = (n_edges >= 64) ? 128 : (2 * n_edges);
    const int istride = detect_idx_stride(x_idx, probe_n);

    // ---- one-time: W1 -> fp16 B^T[n][k], XOR-swizzled 16B chunks ----
    for (int i = tid; i < NHID * K2; i += THREADS) {
        int n = i & (NHID - 1);
        int k = i >> 7;
        __half h = __float2half_rn(W1[k * NHID + n]);
        uint32_t off = (uint32_t)n * 512u + (uint32_t)(((k >> 3) ^ (n & 7)) << 4)
                     + (uint32_t)(k & 7) * 2u;
        *(__half*)(smem + SM_B + off) = h;
    }
    if (tid < NHID) {
        ((float*)(smem + SM_B1))[tid] = bias1[tid];
        ((float*)(smem + SM_W2))[tid] = W2[tid];
    }
    const float b2 = bias2[0];
    __syncthreads();

    // epilogue constants: cols n = nw*32 + nt*8 + (lane&3)*2 + {0,1}
    float b1v[8], w2v[8];
    {
        const float* b1s = (const float*)(smem + SM_B1);
        const float* w2s = (const float*)(smem + SM_W2);
        #pragma unroll
        for (int nt = 0; nt < 4; nt++) {
            int n = nw * 32 + nt * 8 + (lane & 3) * 2;
            b1v[2*nt] = b1s[n];   b1v[2*nt+1] = b1s[n+1];
            w2v[2*nt] = w2s[n];   w2v[2*nt+1] = w2s[n+1];
        }
    }

    // ldmatrix lane addressing
    const uint32_t aAddr = sb + SM_A + (uint32_t)mw * 16 * ARSTR
                         + (uint32_t)(lane & 15) * ARSTR + (uint32_t)(lane >> 4) * 16;
    const uint32_t sw   = (uint32_t)(lane & 7);
    const uint32_t kbit = (uint32_t)((lane >> 3) & 1);
    uint32_t bBase[2];
    {
        uint32_t row_l = (uint32_t)((lane & 7) + ((lane >> 4) << 3));  // 0..15
        #pragma unroll
        for (int pr = 0; pr < 2; pr++)
            bBase[pr] = sb + SM_B + ((uint32_t)nw * 32 + (uint32_t)pr * 16 + row_l) * 512u;
    }

    float* part = (float*)(smem + SM_PART);

    // gather slot geometry: 32 rows x 64 float4-slots; 8 slots/thread
    const int c4   = tid & 63;
    const int row0 = tid >> 6;          // rows row0 + 4*it, it<8
    const bool is_x = (c4 < 32);
    const int  src4 = c4 & 31;
    const int* idx_base = is_x ? x_idx : y_idx;

    const int stride_t = (int)gridDim.x;

    // ---- prologue: gather first tile into registers ----
    float4 reg[8];
    {
        int tile = blockIdx.x;
        if (tile < n_tiles) {
            int e0 = tile * TILE_E;
            #pragma unroll
            for (int it = 0; it < 8; it++) {
                int e = e0 + row0 + it * 4;
                int es = (e < n_edges) ? e : 0;
                int node = __ldg(idx_base + (size_t)es * istride);
                reg[it] = __ldg((const float4*)(inputs + (size_t)node * NHID) + src4);
            }
        }
    }

    for (int tile = blockIdx.x; tile < n_tiles; tile += stride_t) {
        const int e0 = tile * TILE_E;

        // ---- convert + store A (prev MMA finished at the epilogue barrier) ----
        #pragma unroll
        for (int it = 0; it < 8; it++) {
            float4 v = reg[it];
            __half2 h0 = __float22half2_rn(make_float2(v.x, v.y));
            __half2 h1 = __float22half2_rn(make_float2(v.z, v.w));
            uint32_t row = (uint32_t)(row0 + it * 4);
            *(uint2*)(smem + SM_A + row * ARSTR + (uint32_t)c4 * 8u) =
                make_uint2(*(uint32_t*)&h0, *(uint32_t*)&h1);
        }
        __syncthreads();   // A ready

        // ---- prefetch next tile into registers (latency hides under MMA) ----
        {
            int ntile = tile + stride_t;
            if (ntile < n_tiles) {
                int ne0 = ntile * TILE_E;
                #pragma unroll
                for (int it = 0; it < 8; it++) {
                    int e = ne0 + row0 + it * 4;
                    int es = (e < n_edges) ? e : 0;
                    int node = __ldg(idx_base + (size_t)es * istride);
                    reg[it] = __ldg((const float4*)(inputs + (size_t)node * NHID) + src4);
                }
            }
        }

        // ---- MMA mainloop: 16 K-chunks x 2 pr x 2 ----
        float c[4][4];
        #pragma unroll
        for (int nt = 0; nt < 4; nt++)
            #pragma unroll
            for (int j = 0; j < 4; j++) c[nt][j] = 0.f;

        #pragma unroll
        for (int kc = 0; kc < 16; kc++) {
            uint32_t a[4];
            ldsm_x4(aAddr + (uint32_t)kc * 32u, a);
            uint32_t csw = ((uint32_t)(2 * kc) + kbit) ^ sw;
            #pragma unroll
            for (int pr = 0; pr < 2; pr++) {
                uint32_t b[4];
                ldsm_x4(bBase[pr] + (csw << 4), b);
                mma_fp16(c[2*pr],     a, b[0], b[1]);
                mma_fp16(c[2*pr + 1], a, b[2], b[3]);
            }
        }

        // ---- epilogue: bias + relu + W2 dot, 4-lane reduce, partials ----
        float p0 = 0.f, p1 = 0.f;
        #pragma unroll
        for (int nt = 0; nt < 4; nt++) {
            p0 = fmaf(fmaxf(c[nt][0] + b1v[2*nt],   0.f), w2v[2*nt],   p0);
            p0 = fmaf(fmaxf(c[nt][1] + b1v[2*nt+1], 0.f), w2v[2*nt+1], p0);
            p1 = fmaf(fmaxf(c[nt][2] + b1v[2*nt],   0.f), w2v[2*nt],   p1);
            p1 = fmaf(fmaxf(c[nt][3] + b1v[2*nt+1], 0.f), w2v[2*nt+1], p1);
        }
        p0 += __shfl_xor_sync(0xffffffffu, p0, 1, 32);
        p0 += __shfl_xor_sync(0xffffffffu, p0, 2, 32);
        p1 += __shfl_xor_sync(0xffffffffu, p1, 1, 32);
        p1 += __shfl_xor_sync(0xffffffffu, p1, 2, 32);

        if ((lane & 3) == 0) {
            const int g = lane >> 2;
            part[nw * 32 + mw * 16 + g]     = p0;
            part[nw * 32 + mw * 16 + g + 8] = p1;
        }
        __syncthreads();   // also protects A until all MMAs done

        if (tid < TILE_E) {
            int e = e0 + tid;
            if (e < n_edges) {
                float s = part[tid] + part[32 + tid] + part[64 + tid] + part[96 + tid] + b2;
                out[e] = 1.f / (1.f + __expf(-s));
            }
        }
    }
}

extern "C" void kernel_launch(void* const* d_in, const int* in_sizes, int n_in,
                              void* d_out, int out_size) {
    const float* inputs = (const float*)d_in[0];
    const int*   xi     = (const int*)d_in[1];
    const int*   yi     = (const int*)d_in[2];
    const float* W1     = (const float*)d_in[3];
    const float* b1     = (const float*)d_in[4];
    const float* W2     = (const float*)d_in[5];
    const float* b2     = (const float*)d_in[6];
    float* out = (float*)d_out;

    const int n_edges = in_sizes[1];
    const int n_tiles = (n_edges + TILE_E - 1) / TILE_E;

    cudaFuncSetAttribute(mlp_decoder_hmma3_kernel,
                         cudaFuncAttributeMaxDynamicSharedMemorySize, SM_TOTAL);

    int dev = 0, nsm = 148;
    cudaGetDevice(&dev);
    cudaDeviceGetAttribute(&nsm, cudaDevAttrMultiProcessorCount, dev);
    int grid = 2 * nsm;
    if (grid > n_tiles) grid = n_tiles;

    mlp_decoder_hmma3_kernel<<<grid, THREADS, SM_TOTAL>>>(
        inputs, xi, yi, W1, b1, W2, b2, out, n_edges, n_tiles);
}

// round 8
// speedup vs baseline: 7.9868x; 1.0326x over previous
#include <cuda_runtime.h>
#include <cuda_fp16.h>
#include <cstdint>

#define NHID    128
#define K2      256
#define TILE_E  32
#define THREADS 256

// edge tile: fp16, padded rows of 264 halves = 528 B (odd 16B count -> conflict-free ldmatrix)
#define ERSTR   528

// ---- SMEM layout (bytes) ----
// [0, 65536): W1^T fp16 XOR-swizzled (init only), then REUSED as edge tile (32 x 528 = 16896)
#define SM_W1    0
#define SM_E     0
#define SM_PART  65536     // f32[8][32]
#define SM_TOTAL 66816

__device__ __forceinline__ uint32_t smem_u32(const void* p) {
    uint32_t a;
    asm("{ .reg .u64 t; cvta.to.shared.u64 t, %1; cvt.u32.u64 %0, t; }" : "=r"(a) : "l"(p));
    return a;
}
__device__ __forceinline__ void ldsm_x4(uint32_t addr, uint32_t r[4]) {
    asm volatile("ldmatrix.sync.aligned.m8n8.x4.shared.b16 {%0,%1,%2,%3}, [%4];"
                 : "=r"(r[0]), "=r"(r[1]), "=r"(r[2]), "=r"(r[3]) : "r"(addr));
}
__device__ __forceinline__ void mma_fp16(float c[4], const uint32_t a[4], uint32_t b0, uint32_t b1) {
    asm volatile("mma.sync.aligned.m16n8k16.row.col.f32.f16.f16.f32 "
                 "{%0,%1,%2,%3}, {%4,%5,%6,%7}, {%8,%9}, {%0,%1,%2,%3};"
                 : "+f"(c[0]), "+f"(c[1]), "+f"(c[2]), "+f"(c[3])
                 : "r"(a[0]), "r"(a[1]), "r"(a[2]), "r"(a[3]), "r"(b0), "r"(b1));
}

// int32 data -> stride 1; int64 (LE, values < 1e5) -> every odd word 0 -> stride 2
__device__ __forceinline__ int detect_idx_stride(const int* p, int n_words) {
    int stride = 2;
    #pragma unroll 1
    for (int i = 1; i < n_words; i += 2)
        if (p[i] != 0) { stride = 1; break; }
    return stride;
}

__global__ void __launch_bounds__(THREADS, 2)
mlp_decoder_hmma4_kernel(const float* __restrict__ inputs,
                         const int* __restrict__ x_idx,
                         const int* __restrict__ y_idx,
                         const float* __restrict__ W1,
                         const float* __restrict__ bias1,
                         const float* __restrict__ W2,
                         const float* __restrict__ bias2,
                         float* __restrict__ out,
                         int n_edges, int n_tiles)
{
    extern __shared__ char smem[];
    const uint32_t sb  = smem_u32(smem);
    const int tid  = threadIdx.x;
    const int lane = tid & 31;
    const int wid  = tid >> 5;    // warp owns output cols [wid*16, wid*16+16)

    const int probe_n = (n_edges >= 64) ? 128 : (2 * n_edges);
    const int istride = detect_idx_stride(x_idx, probe_n);

    // ---- init: W1 -> fp16 W1^T[n][k] in smem, XOR-swizzled 16B chunks ----
    for (int i = tid; i < NHID * K2; i += THREADS) {
        int n = i & (NHID - 1);
        int k = i >> 7;
        __half h = __float2half_rn(W1[k * NHID + n]);
        uint32_t off = (uint32_t)n * 512u + (uint32_t)(((k >> 3) ^ (n & 7)) << 4)
                     + (uint32_t)(k & 7) * 2u;
        *(__half*)(smem + SM_W1 + off) = h;
    }
    __syncthreads();

    // ---- load per-warp A fragments (W1 cols 16*wid..+16, all K) into registers ----
    uint32_t aF[16][4];
    {
        uint32_t row = (uint32_t)(wid * 16 + (lane & 15));
        uint32_t rsw = (row & 7);
        #pragma unroll
        for (int kc = 0; kc < 16; kc++) {
            uint32_t chunk = (uint32_t)(2 * kc) + (uint32_t)(lane >> 4);
            uint32_t addr = sb + SM_W1 + row * 512u + ((chunk ^ rsw) << 4);
            ldsm_x4(addr, aF[kc]);
        }
    }
    // epilogue constants: this thread covers output cols j0, j1
    const int j0 = wid * 16 + (lane >> 2);
    const int j1 = j0 + 8;
    const float b10 = bias1[j0], b11 = bias1[j1];
    const float w20 = W2[j0],    w21 = W2[j1];
    const float b2v = bias2[0];
    __syncthreads();   // W1 smem region now free -> edge tile

    // edge b-frag ldsm addressing
    const uint32_t row_l = (uint32_t)((lane & 7) + ((lane >> 4) << 3));
    const uint32_t kb    = (uint32_t)((lane >> 3) & 1);
    const uint32_t eb0   = sb + SM_E + row_l * ERSTR + kb * 16u;
    const uint32_t eb1   = eb0 + 16u * ERSTR;

    float* part = (float*)(smem + SM_PART);

    // gather geometry: 32 rows x 64 fp32-16B slots; 8 slots/thread
    const int c4   = tid & 63;
    const int row0 = tid >> 6;          // rows row0 + 4*it
    const int  src4 = c4 & 31;
    const int* idx_base = (c4 < 32) ? x_idx : y_idx;

    const int stride_t = (int)gridDim.x;

    // ---- prologue: gather first tile ----
    float4 st[8];
    {
        int tile = blockIdx.x;
        if (tile < n_tiles) {
            int e0 = tile * TILE_E;
            #pragma unroll
            for (int it = 0; it < 8; it++) {
                int e = e0 + row0 + it * 4;
                int es = (e < n_edges) ? e : 0;
                int node = __ldg(idx_base + (size_t)es * istride);
                st[it] = __ldg((const float4*)(inputs + (size_t)node * NHID) + src4);
            }
        }
    }

    for (int tile = blockIdx.x; tile < n_tiles; tile += stride_t) {
        const int e0 = tile * TILE_E;

        // ---- convert + store edge tile (fp16) ----
        #pragma unroll
        for (int it = 0; it < 8; it++) {
            float4 v = st[it];
            __half2 h0 = __float22half2_rn(make_float2(v.x, v.y));
            __half2 h1 = __float22half2_rn(make_float2(v.z, v.w));
            uint32_t row = (uint32_t)(row0 + it * 4);
            *(uint2*)(smem + SM_E + row * ERSTR + (uint32_t)c4 * 8u) =
                make_uint2(*(uint32_t*)&h0, *(uint32_t*)&h1);
        }
        __syncthreads();   // edge tile ready

        // ---- prefetch next tile (latency hides under MMAs) ----
        {
            int ntile = tile + stride_t;
            if (ntile < n_tiles) {
                int ne0 = ntile * TILE_E;
                #pragma unroll
                for (int it = 0; it < 8; it++) {
                    int e = ne0 + row0 + it * 4;
                    int es = (e < n_edges) ? e : 0;
                    int node = __ldg(idx_base + (size_t)es * istride);
                    st[it] = __ldg((const float4*)(inputs + (size_t)node * NHID) + src4);
                }
            }
        }

        // ---- MMA: 16 kc x (2 ldsm + 4 mma); A from registers ----
        float c[4][4];
        #pragma unroll
        for (int et = 0; et < 4; et++)
            #pragma unroll
            for (int j = 0; j < 4; j++) c[et][j] = 0.f;

        #pragma unroll
        for (int kc = 0; kc < 16; kc++) {
            uint32_t b0[4], b1f[4];
            ldsm_x4(eb0 + (uint32_t)kc * 32u, b0);   // edges 0-15
            ldsm_x4(eb1 + (uint32_t)kc * 32u, b1f);  // edges 16-31
            mma_fp16(c[0], aF[kc], b0[0],  b0[1]);   // edges 0-7
            mma_fp16(c[1], aF[kc], b0[2],  b0[3]);   // edges 8-15
            mma_fp16(c[2], aF[kc], b1f[0], b1f[1]);  // edges 16-23
            mma_fp16(c[3], aF[kc], b1f[2], b1f[3]);  // edges 24-31
        }

        // ---- epilogue ----
        // c[et]: rows = output cols j0 (c0,c1) / j1 (c2,c3); cols = edges et*8 + 2*(lane&3) + {0,1}
        #pragma unroll
        for (int et = 0; et < 4; et++) {
            float pa = fmaf(fmaxf(c[et][0] + b10, 0.f), w20,
                            fmaxf(c[et][2] + b11, 0.f) * w21);
            float pb = fmaf(fmaxf(c[et][1] + b10, 0.f), w20,
                            fmaxf(c[et][3] + b11, 0.f) * w21);
            // reduce over the 8 lane-groups (16 output cols of this warp)
            pa += __shfl_xor_sync(0xffffffffu, pa, 4, 32);
            pa += __shfl_xor_sync(0xffffffffu, pa, 8, 32);
            pa += __shfl_xor_sync(0xffffffffu, pa, 16, 32);
            pb += __shfl_xor_sync(0xffffffffu, pb, 4, 32);
            pb += __shfl_xor_sync(0xffffffffu, pb, 8, 32);
            pb += __shfl_xor_sync(0xffffffffu, pb, 16, 32);
            if (lane < 4) {
                int ea = et * 8 + 2 * lane;
                part[wid * 32 + ea]     = pa;
                part[wid * 32 + ea + 1] = pb;
            }
        }
        __syncthreads();   // part ready; edge tile free

        if (tid < TILE_E) {
            int e = e0 + tid;
            if (e < n_edges) {
                float s = b2v;
                #pragma unroll
                for (int w = 0; w < 8; w++) s += part[w * 32 + tid];
                out[e] = 1.f / (1.f + __expf(-s));
            }
        }
    }
}

extern "C" void kernel_launch(void* const* d_in, const int* in_sizes, int n_in,
                              void* d_out, int out_size) {
    const float* inputs = (const float*)d_in[0];
    const int*   xi     = (const int*)d_in[1];
    const int*   yi     = (const int*)d_in[2];
    const float* W1     = (const float*)d_in[3];
    const float* b1     = (const float*)d_in[4];
    const float* W2     = (const float*)d_in[5];
    const float* b2     = (const float*)d_in[6];
    float* out = (float*)d_out;

    const int n_edges = in_sizes[1];
    const int n_tiles = (n_edges + TILE_E - 1) / TILE_E;

    cudaFuncSetAttribute(mlp_decoder_hmma4_kernel,
                         cudaFuncAttributeMaxDynamicSharedMemorySize, SM_TOTAL);

    int dev = 0, nsm = 148;
    cudaGetDevice(&dev);
    cudaDeviceGetAttribute(&nsm, cudaDevAttrMultiProcessorCount, dev);
    int grid = 2 * nsm;
    if (grid > n_tiles) grid = n_tiles;

    mlp_decoder_hmma4_kernel<<<grid, THREADS, SM_TOTAL>>>(
        inputs, xi, yi, W1, b1, W2, b2, out, n_edges, n_tiles);
}